// round 5
// baseline (speedup 1.0000x reference)
#include <cuda_runtime.h>

#define HH 512
#define WW 512
#define BB 2

// Packed row-pass result, one uint16 per pixel:
//   bit15 = mask (1 = fg), bits[0:15) = row distance to nearest OPPOSITE-class
//   pixel (0x7fff sentinel = none in this row). 1 MB total.
__device__ unsigned short g_pack16[BB * HH * WW];

// ---------------------------------------------------------------------------
// Kernel A: row pass via 512-bit row bitmask + word scans. 2 rows per block
// (1024 threads), 1 pixel per thread. Nearest opposite bit via ffs/clz on the
// pixel's own word (expected O(1)); rare fallback walks adjacent words.
// ---------------------------------------------------------------------------
__global__ void __launch_bounds__(1024) row_pass(const float* __restrict__ gt) {
    const int b = blockIdx.x >> 8;           // blockIdx.x = b*256 + yPair
    const int rl = threadIdx.x >> 9;         // which row of the pair
    const int x = threadIdx.x & 511;
    const int y = ((blockIdx.x & 255) << 1) + rl;

    __shared__ unsigned int sw[2][WW / 32];  // 2 x 16 words

    const float v = gt[((size_t)b * HH + y) * WW + x];
    const unsigned int m = (v == 1.0f) ? 1u : 0u;
    const unsigned int bits = __ballot_sync(0xFFFFFFFFu, m != 0u);
    if ((x & 31) == 0) sw[rl][x >> 5] = bits;
    __syncthreads();

    const unsigned int xorm = m ? 0xFFFFFFFFu : 0u;  // opp(word) = word ^ xorm
    const int w0 = x >> 5, off = x & 31;
    const unsigned int cur = sw[rl][w0] ^ xorm;

    int right = 0x7fff;
    {
        const unsigned int hi = cur & (0xFFFFFFFEu << off);
        if (hi) {
            right = (__ffs(hi) - 1) - off;
        } else {
            #pragma unroll 1
            for (int w = w0 + 1; w < WW / 32; ++w) {
                const unsigned int t = sw[rl][w] ^ xorm;
                if (t) { right = (w << 5) + (__ffs(t) - 1) - x; break; }
            }
        }
    }
    int left = 0x7fff;
    {
        const unsigned int lo = cur & ((1u << off) - 1u);
        if (lo) {
            left = off - (31 - __clz(lo));
        } else {
            #pragma unroll 1
            for (int w = w0 - 1; w >= 0; --w) {
                const unsigned int t = sw[rl][w] ^ xorm;
                if (t) { left = x - ((w << 5) + (31 - __clz(t))); break; }
            }
        }
    }

    const unsigned int d = (unsigned int)min(min(left, right), 0x7fff);
    g_pack16[((size_t)b * HH + y) * WW + x] = (unsigned short)(d | (m << 15));
}

// ---------------------------------------------------------------------------
// Kernel B: column pass with SHARED-MEMORY staged column strips.
// Block = 2 pixel-pairs (4 columns) x all 512 rows, 1024 threads, one
// pixel-pair per thread. One global load per thread (chain-free), then the
// exact adaptive-window scan (stop when r^2 >= best; provably exact) runs
// against LDS (29 cyc) instead of L2 (~250 cyc). Opposite plane only.
// Fused epilogue: out = (m ? -1 : +1) * sqrt(best).
// ---------------------------------------------------------------------------
__global__ void __launch_bounds__(1024) col_pass(float* __restrict__ out) {
    const int b = blockIdx.x >> 7;           // blockIdx.x = b*128 + tile
    const int tile = blockIdx.x & 127;
    const int p = threadIdx.x >> 9;          // which pair of the tile (0/1)
    const int row = threadIdx.x & 511;
    const int pair = (tile << 1) + p;        // pair index in [0, 256)

    __shared__ unsigned int sw[2][HH];       // [pair-in-tile][row]

    const unsigned int u =
        reinterpret_cast<const unsigned int*>(g_pack16)
            [((size_t)b * HH + row) * (WW / 2) + pair];
    sw[p][row] = u;
    __syncthreads();

    const unsigned int mA = (u >> 15) & 1u;
    const unsigned int mB = (u >> 31) & 1u;
    const int roA = (int)(u & 0x7fffu);
    const int roB = (int)((u >> 16) & 0x7fffu);
    float bestA = (float)(roA * roA);
    float bestB = (float)(roB * roB);

    const unsigned int* __restrict__ scol = sw[p];

    #pragma unroll 1
    for (int r = 1; r < HH; ++r) {
        const float rr = (float)(r * r);
        if (rr >= bestA && rr >= bestB) break;
        const int up = row - r, dn = row + r;
        if (up >= 0) {
            const unsigned int w = scol[up];
            const int ra = (int)(w & 0x7fffu), rb = (int)((w >> 16) & 0x7fffu);
            const float fa = (((w >> 15) & 1u) != mA) ? 0.0f : (float)(ra * ra);
            const float fb = (((w >> 31) & 1u) != mB) ? 0.0f : (float)(rb * rb);
            bestA = fminf(bestA, fa + rr);
            bestB = fminf(bestB, fb + rr);
        }
        if (dn < HH) {
            const unsigned int w = scol[dn];
            const int ra = (int)(w & 0x7fffu), rb = (int)((w >> 16) & 0x7fffu);
            const float fa = (((w >> 15) & 1u) != mA) ? 0.0f : (float)(ra * ra);
            const float fb = (((w >> 31) & 1u) != mB) ? 0.0f : (float)(rb * rb);
            bestA = fminf(bestA, fa + rr);
            bestB = fminf(bestB, fb + rr);
        }
    }

    float2 o;
    o.x = (mA ? -1.0f : 1.0f) * sqrtf(bestA);
    o.y = (mB ? -1.0f : 1.0f) * sqrtf(bestB);
    reinterpret_cast<float2*>(out)[((size_t)b * HH + row) * (WW / 2) + pair] = o;
}

extern "C" void kernel_launch(void* const* d_in, const int* in_sizes, int n_in,
                              void* d_out, int out_size) {
    const float* gt = (const float*)d_in[0];
    float* out = (float*)d_out;
    (void)in_sizes; (void)n_in; (void)out_size;

    row_pass<<<BB * HH / 2, 1024>>>(gt);
    col_pass<<<BB * (WW / 2) / 2, 1024>>>(out);
}